// round 3
// baseline (speedup 1.0000x reference)
#include <cuda_runtime.h>

// ---------------------------------------------------------------------------
// DILATE loss: pairwise sq-dist -> soft-DTW forward -> soft-DTW gradient ->
// shape + temporal terms -> scalar.
// B=128, T=256, D=64, gamma=0.01, alpha=0.5, eps=1e-8, BIG=1e10.
// ---------------------------------------------------------------------------

#define BATCH 128
#define TLEN  256
#define DDIM  64
#define NDIAG 511            // 2*TLEN - 1
#define GAMMA_F 0.01f
#define INVG    100.0f
#define BIGV    1e10f

// Scratch in diagonal-major layout: [b][d][i], slot (d,i) holds cell (i, j=d-i).
__device__ float g_D[(size_t)BATCH * NDIAG * TLEN];
__device__ float g_R[(size_t)BATCH * NDIAG * TLEN];
__device__ float g_shape[BATCH];
__device__ float g_num[BATCH];
__device__ float g_den[BATCH];

__device__ __forceinline__ size_t DI(int b, int d, int i) {
    return ((size_t)b * NDIAG + d) * TLEN + i;
}

// ---------------------------------------------------------------------------
// Kernel 1: pairwise squared distances, written directly in diagonal layout.
// Grid: (4, 4, 128) tiles of 64x64, 256 threads, 4x4 register tile per thread.
// ---------------------------------------------------------------------------
__global__ __launch_bounds__(256) void dist_kernel(
    const float* __restrict__ preds, const float* __restrict__ targets)
{
    __shared__ float pool[64 * 65 * 2 + 128];
    float* ps = pool;               // [64][65] preds tile (row-major, pad 65)
    float* ts = pool + 64 * 65;     // [64][65] targets tile
    float* pn = pool + 64 * 65 * 2;       // [64] pred sq-norms
    float* tn = pool + 64 * 65 * 2 + 64;  // [64] targ sq-norms

    const int b  = blockIdx.z;
    const int i0 = blockIdx.y * 64;
    const int j0 = blockIdx.x * 64;
    const int tid = threadIdx.x;

    const float* pb = preds   + (size_t)b * TLEN * DDIM;
    const float* tb = targets + (size_t)b * TLEN * DDIM;

    // Fill smem tiles (coalesced global reads, conflict-free smem writes).
#pragma unroll
    for (int q = 0; q < 16; q++) {
        int idx = q * 256 + tid;
        int r = idx >> 6, k = idx & 63;
        ps[r * 65 + k] = pb[(i0 + r) * DDIM + k];
        ts[r * 65 + k] = tb[(j0 + r) * DDIM + k];
    }
    __syncthreads();

    // Squared norms.
    if (tid < 128) {
        const float* src = (tid < 64) ? ps : ts;
        float* dst = (tid < 64) ? pn : tn;
        int r = tid & 63;
        float s = 0.0f;
#pragma unroll
        for (int k = 0; k < 64; k++) { float v = src[r * 65 + k]; s = fmaf(v, v, s); }
        dst[r] = s;
    }
    __syncthreads();

    const int tx = tid & 15, ty = tid >> 4;
    const int ib = ty * 4, jb = tx * 4;

    float acc[4][4];
#pragma unroll
    for (int r = 0; r < 4; r++)
#pragma unroll
        for (int c = 0; c < 4; c++) acc[r][c] = 0.0f;

#pragma unroll 4
    for (int k = 0; k < 64; k++) {
        float pv[4], tv[4];
#pragma unroll
        for (int r = 0; r < 4; r++) pv[r] = ps[(ib + r) * 65 + k];
#pragma unroll
        for (int c = 0; c < 4; c++) tv[c] = ts[(jb + c) * 65 + k];
#pragma unroll
        for (int r = 0; r < 4; r++)
#pragma unroll
            for (int c = 0; c < 4; c++)
                acc[r][c] = fmaf(pv[r], tv[c], acc[r][c]);
    }

    float pnr[4], tnr[4];
#pragma unroll
    for (int r = 0; r < 4; r++) pnr[r] = pn[ib + r];
#pragma unroll
    for (int c = 0; c < 4; c++) tnr[c] = tn[jb + c];

    __syncthreads();   // everyone done reading ps/ts/pn/tn

    // Stage tile in diagonal layout: buf[tdd][ii], tdd = local i+j (0..126).
    float* buf = pool;   // 127*65 = 8255 floats, fits in pool
#pragma unroll
    for (int r = 0; r < 4; r++)
#pragma unroll
        for (int c = 0; c < 4; c++) {
            int ii = ib + r, jj = jb + c;
            float dv = pnr[r] + tnr[c] - 2.0f * acc[r][c];
            dv = fmaxf(dv, 0.0f);
            buf[(ii + jj) * 65 + ii] = dv;
        }
    __syncthreads();

    // Coalesced diagonal write-out: warp lanes sweep ii within a fixed tdd.
    for (int base = 0; base < 128; base += 4) {
        int tdd = base + (tid >> 6);
        int ii  = tid & 63;
        if (tdd < 127) {
            int jj = tdd - ii;
            if (jj >= 0 && jj < 64) {
                g_D[DI(b, i0 + j0 + tdd, i0 + ii)] = buf[tdd * 65 + ii];
            }
        }
    }
}

// ---------------------------------------------------------------------------
// Kernel 2: soft-DTW forward wavefront. 1 block per batch, thread i = row i.
// Rotating 3-diagonal smem buffers; slot [i+1] holds position i, [0] = BIG pad.
// ---------------------------------------------------------------------------
__global__ __launch_bounds__(256) void fwd_kernel()
{
    __shared__ float buf[3][258];
    const int b = blockIdx.x;
    const int i = threadIdx.x;

    for (int q = i; q < 3 * 258; q += 256) ((float*)buf)[q] = BIGV;
    __syncthreads();

    float Dc = (i == 0) ? g_D[DI(b, 0, 0)] : 0.0f;
    float Rlast = BIGV;

    for (int d = 0; d < NDIAG; d++) {
        const bool v = (i <= d) && ((d - i) < TLEN);

        // Prefetch next diagonal's D.
        float Dn = 0.0f;
        const int dn = d + 1;
        if (dn < NDIAG && (i <= dn) && ((dn - i) < TLEN))
            Dn = g_D[DI(b, dn, i)];

        float R;
        if (!v) {
            R = BIGV;
        } else if (d == 0) {
            R = Dc;                      // R[0,0] = D[0,0]
        } else {
            const int p1 = (d + 2) % 3;  // diag d-1
            const int p2 = (d + 1) % 3;  // diag d-2
            float z0 = buf[p2][i];       // R[i-1, j-1]
            float z1 = buf[p1][i];       // R[i-1, j  ]
            float z2 = buf[p1][i + 1];   // R[i,   j-1]
            float m = fminf(z0, fminf(z1, z2));
            float s = __expf((m - z0) * INVG)
                    + __expf((m - z1) * INVG)
                    + __expf((m - z2) * INVG);
            R = Dc + m - GAMMA_F * __logf(s);
        }

        g_R[DI(b, d, i)] = R;
        buf[d % 3][i + 1] = R;
        __syncthreads();

        Dc = Dn;
        Rlast = R;
    }

    if (i == 255) g_shape[b] = Rlast;    // R[255,255]
}

// ---------------------------------------------------------------------------
// Kernel 3: soft-DTW gradient (reverse wavefront) + Sum(E), Sum(E*omega).
// E[i,j] = sum over valid successors E' * exp((R'-D'-R[i,j])/gamma).
// ---------------------------------------------------------------------------
__global__ __launch_bounds__(256) void bwd_kernel()
{
    __shared__ float sE[3][257];
    __shared__ float sR[3][257];
    __shared__ float sD[3][257];
    __shared__ float red[16];

    const int b = blockIdx.x;
    const int i = threadIdx.x;

    for (int q = i; q < 3 * 257; q += 256) {
        ((float*)sE)[q] = 0.0f;
        ((float*)sR)[q] = BIGV;
        ((float*)sD)[q] = 0.0f;
    }
    __syncthreads();

    float accS = 0.0f, accW = 0.0f;

    // Prefetch d = 510.
    float Rc = g_R[DI(b, 510, i)];
    float Dc = 0.0f;
    if ((i <= 510) && ((510 - i) < TLEN)) Dc = g_D[DI(b, 510, i)];

    for (int d = NDIAG - 1; d >= 0; d--) {
        const bool v = (i <= d) && ((d - i) < TLEN);
        const int j = d - i;

        // Prefetch diagonal d-1.
        float Rn = 0.0f, Dn = 0.0f;
        if (d > 0) {
            Rn = g_R[DI(b, d - 1, i)];
            if ((i <= d - 1) && ((d - 1 - i) < TLEN)) Dn = g_D[DI(b, d - 1, i)];
        }

        const int c  = d % 3;
        const int n1 = (d + 1) % 3;   // diag d+1
        const int n2 = (d + 2) % 3;   // diag d+2

        float E;
        if (!v) {
            E = 0.0f;
        } else if (d == NDIAG - 1) {
            E = 1.0f;                  // seed at (255,255)
        } else {
            float e = 0.0f;
            if (i < TLEN - 1) {        // successor (i+1, j)
                float a = (sR[n1][i + 1] - sD[n1][i + 1] - Rc) * INVG;
                e = fmaf(sE[n1][i + 1], __expf(a), e);
            }
            if (j < TLEN - 1) {        // successor (i, j+1)
                float a = (sR[n1][i] - sD[n1][i] - Rc) * INVG;
                e = fmaf(sE[n1][i], __expf(a), e);
            }
            if (i < TLEN - 1 && j < TLEN - 1) {  // successor (i+1, j+1)
                float a = (sR[n2][i + 1] - sD[n2][i + 1] - Rc) * INVG;
                e = fmaf(sE[n2][i + 1], __expf(a), e);
            }
            E = e;
        }

        if (v) {
            accS += E;
            float dw = (float)(i - j);
            accW = fmaf(E, dw * dw, accW);
        }

        sE[c][i] = E;
        sR[c][i] = Rc;
        sD[c][i] = Dc;
        __syncthreads();

        Rc = Rn;
        Dc = Dn;
    }

    accW *= (1.0f / (255.0f * 255.0f));   // omega normalization /(T-1)^2

    // Block reduction.
#pragma unroll
    for (int off = 16; off; off >>= 1) {
        accS += __shfl_down_sync(0xFFFFFFFFu, accS, off);
        accW += __shfl_down_sync(0xFFFFFFFFu, accW, off);
    }
    const int w = i >> 5, l = i & 31;
    if (l == 0) { red[w] = accS; red[w + 8] = accW; }
    __syncthreads();
    if (i == 0) {
        float s = 0.0f, wv = 0.0f;
#pragma unroll
        for (int q = 0; q < 8; q++) { s += red[q]; wv += red[q + 8]; }
        g_den[b] = s;
        g_num[b] = wv;
    }
}

// ---------------------------------------------------------------------------
// Kernel 4: final scalar. alignment = E/T, so num/den both carry 1/T.
// loss = 0.5*mean(R_final/T) + 0.5*mean( (SumEw/T) / max(SumE/T, eps) )
// ---------------------------------------------------------------------------
__global__ void final_kernel(float* __restrict__ out)
{
    __shared__ float red[4];
    const int t = threadIdx.x;   // 128 threads, one per batch

    float shape = g_shape[t] * (1.0f / 256.0f);
    float den   = g_den[t]   * (1.0f / 256.0f);
    float num   = g_num[t]   * (1.0f / 256.0f);
    float temporal = num / fmaxf(den, 1e-8f);
    float val = 0.5f * shape + 0.5f * temporal;

#pragma unroll
    for (int off = 16; off; off >>= 1)
        val += __shfl_down_sync(0xFFFFFFFFu, val, off);
    if ((t & 31) == 0) red[t >> 5] = val;
    __syncthreads();
    if (t == 0)
        out[0] = (red[0] + red[1] + red[2] + red[3]) * (1.0f / 128.0f);
}

// ---------------------------------------------------------------------------
extern "C" void kernel_launch(void* const* d_in, const int* in_sizes, int n_in,
                              void* d_out, int out_size)
{
    const float* preds   = (const float*)d_in[0];
    const float* targets = (const float*)d_in[1];

    dist_kernel<<<dim3(4, 4, BATCH), 256>>>(preds, targets);
    fwd_kernel<<<BATCH, 256>>>();
    bwd_kernel<<<BATCH, 256>>>();
    final_kernel<<<1, 128>>>((float*)d_out);
}

// round 4
// speedup vs baseline: 1.5264x; 1.5264x over previous
#include <cuda_runtime.h>

// ---------------------------------------------------------------------------
// DILATE loss: pairwise sq-dist -> soft-DTW forward -> soft-DTW gradient ->
// shape + temporal terms -> scalar.
// B=128, T=256, D=64, gamma=0.01, alpha=0.5, eps=1e-8, BIG=1e10.
//
// Wavefront kernels use an 8-deep register prefetch ring over diagonal-major
// scratch (padded +8 diags each side) to hide DRAM/L2 latency behind the
// 511-step barrier-sequential recursion.
// ---------------------------------------------------------------------------

#define BATCH 128
#define TLEN  256
#define DDIM  64
#define NDIAG 511            // 2*TLEN - 1
#define PF    8              // prefetch depth (register ring)
#define NDIAGT (NDIAG + 2 * PF)
#define BIGV  1e10f
// exp(x/gamma) = exp2(x * KE2);  KE2 = (1/gamma)*log2(e) = 100*1.442695...
#define KE2   144.26950408889634f
// gamma * ln(2): R = D + m - KL*log2(sum)
#define KL    0.006931471805599453f

// Scratch, diagonal-major: [b][d+PF][i], cell (i, j=d-i).
__device__ float g_D[(size_t)BATCH * NDIAGT * TLEN];
__device__ float g_R[(size_t)BATCH * NDIAGT * TLEN];
__device__ float g_shape[BATCH];
__device__ float g_num[BATCH];
__device__ float g_den[BATCH];

__device__ __forceinline__ size_t DI(int b, int d, int i) {
    return ((size_t)b * NDIAGT + (d + PF)) * TLEN + i;
}

// ---------------------------------------------------------------------------
// Kernel 1: pairwise squared distances, written directly in diagonal layout.
// Grid: (4, 4, 128) tiles of 64x64, 256 threads, 4x4 register tile per thread.
// ---------------------------------------------------------------------------
__global__ __launch_bounds__(256) void dist_kernel(
    const float* __restrict__ preds, const float* __restrict__ targets)
{
    __shared__ float pool[64 * 65 * 2 + 128];
    float* ps = pool;               // [64][65] preds tile
    float* ts = pool + 64 * 65;     // [64][65] targets tile
    float* pn = pool + 64 * 65 * 2;       // [64] pred sq-norms
    float* tn = pool + 64 * 65 * 2 + 64;  // [64] targ sq-norms

    const int b  = blockIdx.z;
    const int i0 = blockIdx.y * 64;
    const int j0 = blockIdx.x * 64;
    const int tid = threadIdx.x;

    const float* pb = preds   + (size_t)b * TLEN * DDIM;
    const float* tb = targets + (size_t)b * TLEN * DDIM;

#pragma unroll
    for (int q = 0; q < 16; q++) {
        int idx = q * 256 + tid;
        int r = idx >> 6, k = idx & 63;
        ps[r * 65 + k] = pb[(i0 + r) * DDIM + k];
        ts[r * 65 + k] = tb[(j0 + r) * DDIM + k];
    }
    __syncthreads();

    if (tid < 128) {
        const float* src = (tid < 64) ? ps : ts;
        float* dst = (tid < 64) ? pn : tn;
        int r = tid & 63;
        float s = 0.0f;
#pragma unroll
        for (int k = 0; k < 64; k++) { float v = src[r * 65 + k]; s = fmaf(v, v, s); }
        dst[r] = s;
    }
    __syncthreads();

    const int tx = tid & 15, ty = tid >> 4;
    const int ib = ty * 4, jb = tx * 4;

    float acc[4][4];
#pragma unroll
    for (int r = 0; r < 4; r++)
#pragma unroll
        for (int c = 0; c < 4; c++) acc[r][c] = 0.0f;

#pragma unroll 4
    for (int k = 0; k < 64; k++) {
        float pv[4], tv[4];
#pragma unroll
        for (int r = 0; r < 4; r++) pv[r] = ps[(ib + r) * 65 + k];
#pragma unroll
        for (int c = 0; c < 4; c++) tv[c] = ts[(jb + c) * 65 + k];
#pragma unroll
        for (int r = 0; r < 4; r++)
#pragma unroll
            for (int c = 0; c < 4; c++)
                acc[r][c] = fmaf(pv[r], tv[c], acc[r][c]);
    }

    float pnr[4], tnr[4];
#pragma unroll
    for (int r = 0; r < 4; r++) pnr[r] = pn[ib + r];
#pragma unroll
    for (int c = 0; c < 4; c++) tnr[c] = tn[jb + c];

    __syncthreads();

    // Stage tile in diagonal layout: buf[tdd][ii], tdd = local i+j (0..126).
    float* buf = pool;   // 127*65 = 8255 floats, fits
#pragma unroll
    for (int r = 0; r < 4; r++)
#pragma unroll
        for (int c = 0; c < 4; c++) {
            int ii = ib + r, jj = jb + c;
            float dv = pnr[r] + tnr[c] - 2.0f * acc[r][c];
            dv = fmaxf(dv, 0.0f);
            buf[(ii + jj) * 65 + ii] = dv;
        }
    __syncthreads();

    for (int base = 0; base < 128; base += 4) {
        int tdd = base + (tid >> 6);
        int ii  = tid & 63;
        if (tdd < 127) {
            int jj = tdd - ii;
            if (jj >= 0 && jj < 64) {
                g_D[DI(b, i0 + j0 + tdd, i0 + ii)] = buf[tdd * 65 + ii];
            }
        }
    }
}

// ---------------------------------------------------------------------------
// Kernel 2: soft-DTW forward wavefront, 8-deep D prefetch ring.
// ---------------------------------------------------------------------------
__global__ __launch_bounds__(256) void fwd_kernel()
{
    __shared__ float buf[3][258];
    const int b = blockIdx.x;
    const int i = threadIdx.x;

    for (int q = i; q < 3 * 258; q += 256) ((float*)buf)[q] = BIGV;
    __syncthreads();

    const float* Dp = g_D + ((size_t)b * NDIAGT + PF) * TLEN + i;
    float*       Rp = g_R + ((size_t)b * NDIAGT + PF) * TLEN + i;

    float ring[PF];
#pragma unroll
    for (int k = 0; k < PF; k++) ring[k] = Dp[k * TLEN];

    float Rlast = BIGV;

    auto step = [&](int d, int k) {
        float Dc = ring[k];
        ring[k] = Dp[(d + PF) * TLEN];   // refill: consumed PF iters later

        const bool v = (i <= d) && ((d - i) < TLEN);
        float R;
        if (!v) {
            R = BIGV;
        } else if (d == 0) {
            R = Dc;                       // R[0,0] = D[0,0]
        } else {
            const int p1 = (d + 2) % 3;   // diag d-1
            const int p2 = (d + 1) % 3;   // diag d-2
            float z0 = buf[p2][i];        // R[i-1, j-1]
            float z1 = buf[p1][i];        // R[i-1, j  ]
            float z2 = buf[p1][i + 1];    // R[i,   j-1]
            float m = fminf(z0, fminf(z1, z2));
            float s = exp2f((m - z0) * KE2) + exp2f((m - z1) * KE2)
                    + exp2f((m - z2) * KE2);
            R = Dc + m - KL * __log2f(s);
        }

        Rp[d * TLEN] = R;
        buf[d % 3][i + 1] = R;
        __syncthreads();
        Rlast = R;
    };

    for (int d0 = 0; d0 < 504; d0 += PF) {
#pragma unroll
        for (int k = 0; k < PF; k++) step(d0 + k, k);
    }
#pragma unroll
    for (int k = 0; k < 7; k++) step(504 + k, k);   // d = 504..510

    if (i == 255) g_shape[b] = Rlast;    // R[255,255]
}

// ---------------------------------------------------------------------------
// Kernel 3: soft-DTW gradient (reverse wavefront), 8-deep R/D prefetch rings.
// E[i,j] = sum over valid successors E' * exp2(Q' - R[i,j]*KE2),
// Q = (R - D) * KE2 stored once per cell in smem.
// ---------------------------------------------------------------------------
__global__ __launch_bounds__(256) void bwd_kernel()
{
    __shared__ float sE[3][257];
    __shared__ float sQ[3][257];
    __shared__ float red[16];

    const int b = blockIdx.x;
    const int i = threadIdx.x;

    for (int q = i; q < 3 * 257; q += 256) {
        ((float*)sE)[q] = 0.0f;
        ((float*)sQ)[q] = 0.0f;
    }
    __syncthreads();

    const float* Rp = g_R + ((size_t)b * NDIAGT + PF) * TLEN + i;
    const float* Dp = g_D + ((size_t)b * NDIAGT + PF) * TLEN + i;

    float rR[PF], rD[PF];
#pragma unroll
    for (int k = 0; k < PF; k++) {
        rR[k] = Rp[(510 - k) * TLEN];
        rD[k] = Dp[(510 - k) * TLEN];
    }

    float accS = 0.0f, accW = 0.0f;

    auto step = [&](int dd, int k) {
        const int d = 510 - dd;
        float Rc = rR[k], Dc = rD[k];
        rR[k] = Rp[(d - PF) * TLEN];     // pad region when d < PF: never consumed
        rD[k] = Dp[(d - PF) * TLEN];

        const bool v = (i <= d) && ((d - i) < TLEN);
        const int j = d - i;
        const int c  = d % 3;
        const int n1 = (d + 1) % 3;      // diag d+1
        const int n2 = (d + 2) % 3;      // diag d+2

        float E;
        if (dd == 0) {
            E = (i == 255) ? 1.0f : 0.0f;   // seed at (255,255)
        } else if (!v) {
            E = 0.0f;
        } else {
            float t = Rc * KE2;
            float e = 0.0f;
            if (i < TLEN - 1)                      // successor (i+1, j)
                e = fmaf(sE[n1][i + 1], exp2f(sQ[n1][i + 1] - t), e);
            if (j < TLEN - 1)                      // successor (i, j+1)
                e = fmaf(sE[n1][i], exp2f(sQ[n1][i] - t), e);
            if (i < TLEN - 1 && j < TLEN - 1)      // successor (i+1, j+1)
                e = fmaf(sE[n2][i + 1], exp2f(sQ[n2][i + 1] - t), e);
            E = e;
        }

        if (v) {
            accS += E;
            float dw = (float)(i - j);
            accW = fmaf(E, dw * dw, accW);
        }

        sE[c][i] = E;
        sQ[c][i] = (Rc - Dc) * KE2;
        __syncthreads();
    };

    for (int dd0 = 0; dd0 < 504; dd0 += PF) {
#pragma unroll
        for (int k = 0; k < PF; k++) step(dd0 + k, k);
    }
#pragma unroll
    for (int k = 0; k < 7; k++) step(504 + k, k);   // d = 6..0

    accW *= (1.0f / (255.0f * 255.0f));   // omega /(T-1)^2

#pragma unroll
    for (int off = 16; off; off >>= 1) {
        accS += __shfl_down_sync(0xFFFFFFFFu, accS, off);
        accW += __shfl_down_sync(0xFFFFFFFFu, accW, off);
    }
    const int w = i >> 5, l = i & 31;
    if (l == 0) { red[w] = accS; red[w + 8] = accW; }
    __syncthreads();
    if (i == 0) {
        float s = 0.0f, wv = 0.0f;
#pragma unroll
        for (int q = 0; q < 8; q++) { s += red[q]; wv += red[q + 8]; }
        g_den[b] = s;
        g_num[b] = wv;
    }
}

// ---------------------------------------------------------------------------
// Kernel 4: final scalar.
// ---------------------------------------------------------------------------
__global__ void final_kernel(float* __restrict__ out)
{
    __shared__ float red[4];
    const int t = threadIdx.x;   // 128 threads, one per batch

    float shape = g_shape[t] * (1.0f / 256.0f);
    float den   = g_den[t]   * (1.0f / 256.0f);
    float num   = g_num[t]   * (1.0f / 256.0f);
    float temporal = num / fmaxf(den, 1e-8f);
    float val = 0.5f * shape + 0.5f * temporal;

#pragma unroll
    for (int off = 16; off; off >>= 1)
        val += __shfl_down_sync(0xFFFFFFFFu, val, off);
    if ((t & 31) == 0) red[t >> 5] = val;
    __syncthreads();
    if (t == 0)
        out[0] = (red[0] + red[1] + red[2] + red[3]) * (1.0f / 128.0f);
}

// ---------------------------------------------------------------------------
extern "C" void kernel_launch(void* const* d_in, const int* in_sizes, int n_in,
                              void* d_out, int out_size)
{
    const float* preds   = (const float*)d_in[0];
    const float* targets = (const float*)d_in[1];

    dist_kernel<<<dim3(4, 4, BATCH), 256>>>(preds, targets);
    fwd_kernel<<<BATCH, 256>>>();
    bwd_kernel<<<BATCH, 256>>>();
    final_kernel<<<1, 128>>>((float*)d_out);
}

// round 5
// speedup vs baseline: 1.6082x; 1.0536x over previous
#include <cuda_runtime.h>

// ---------------------------------------------------------------------------
// DILATE loss. B=128, T=256, D=64, gamma=0.01, alpha=0.5, eps=1e-8, BIG=1e10.
// Wavefront kernels: 2 diagonals per barrier (halo-redundant), 4-phase register
// prefetch rings, single-instruction MUFU via ex2/lg2.approx.
// ---------------------------------------------------------------------------

#define BATCH 128
#define TLEN  256
#define NDIAG 511            // 2*TLEN - 1
#define PAD   8              // diag padding each side (ring overshoot)
#define NDIAGT (NDIAG + 2 * PAD)
#define BIGV  1e10f
// exp(x/gamma) = exp2(x * KE2);  KE2 = (1/gamma)*log2(e)
#define KE2   144.26950408889634f
// gamma * ln(2)
#define KL    0.006931471805599453f

__device__ float g_D[(size_t)BATCH * NDIAGT * TLEN];
__device__ float g_R[(size_t)BATCH * NDIAGT * TLEN];
__device__ float g_shape[BATCH];
__device__ float g_num[BATCH];
__device__ float g_den[BATCH];

__device__ __forceinline__ size_t DI(int b, int d, int i) {
    return ((size_t)b * NDIAGT + (d + PAD)) * TLEN + i;
}

__device__ __forceinline__ float ex2f_(float x) {
    float y; asm("ex2.approx.ftz.f32 %0, %1;" : "=f"(y) : "f"(x)); return y;
}
__device__ __forceinline__ float lg2f_(float x) {
    float y; asm("lg2.approx.ftz.f32 %0, %1;" : "=f"(y) : "f"(x)); return y;
}
__device__ __forceinline__ float softmin3(float z0, float z1, float z2) {
    float m = fminf(z0, fminf(z1, z2));
    float s = ex2f_((m - z0) * KE2) + ex2f_((m - z1) * KE2)
            + ex2f_((m - z2) * KE2);
    return m - KL * lg2f_(s);
}

// ---------------------------------------------------------------------------
// Kernel 1: pairwise squared distances in diagonal layout.
// ---------------------------------------------------------------------------
__global__ __launch_bounds__(256) void dist_kernel(
    const float* __restrict__ preds, const float* __restrict__ targets)
{
    __shared__ float pool[64 * 65 * 2 + 128];
    float* ps = pool;
    float* ts = pool + 64 * 65;
    float* pn = pool + 64 * 65 * 2;
    float* tn = pool + 64 * 65 * 2 + 64;

    const int b  = blockIdx.z;
    const int i0 = blockIdx.y * 64;
    const int j0 = blockIdx.x * 64;
    const int tid = threadIdx.x;

    const float* pb = preds   + (size_t)b * TLEN * 64;
    const float* tb = targets + (size_t)b * TLEN * 64;

#pragma unroll
    for (int q = 0; q < 16; q++) {
        int idx = q * 256 + tid;
        int r = idx >> 6, k = idx & 63;
        ps[r * 65 + k] = pb[(i0 + r) * 64 + k];
        ts[r * 65 + k] = tb[(j0 + r) * 64 + k];
    }
    __syncthreads();

    if (tid < 128) {
        const float* src = (tid < 64) ? ps : ts;
        float* dst = (tid < 64) ? pn : tn;
        int r = tid & 63;
        float s = 0.0f;
#pragma unroll
        for (int k = 0; k < 64; k++) { float v = src[r * 65 + k]; s = fmaf(v, v, s); }
        dst[r] = s;
    }
    __syncthreads();

    const int tx = tid & 15, ty = tid >> 4;
    const int ib = ty * 4, jb = tx * 4;

    float acc[4][4];
#pragma unroll
    for (int r = 0; r < 4; r++)
#pragma unroll
        for (int c = 0; c < 4; c++) acc[r][c] = 0.0f;

#pragma unroll 4
    for (int k = 0; k < 64; k++) {
        float pv[4], tv[4];
#pragma unroll
        for (int r = 0; r < 4; r++) pv[r] = ps[(ib + r) * 65 + k];
#pragma unroll
        for (int c = 0; c < 4; c++) tv[c] = ts[(jb + c) * 65 + k];
#pragma unroll
        for (int r = 0; r < 4; r++)
#pragma unroll
            for (int c = 0; c < 4; c++)
                acc[r][c] = fmaf(pv[r], tv[c], acc[r][c]);
    }

    float pnr[4], tnr[4];
#pragma unroll
    for (int r = 0; r < 4; r++) pnr[r] = pn[ib + r];
#pragma unroll
    for (int c = 0; c < 4; c++) tnr[c] = tn[jb + c];

    __syncthreads();

    float* buf = pool;   // 127*65 floats
#pragma unroll
    for (int r = 0; r < 4; r++)
#pragma unroll
        for (int c = 0; c < 4; c++) {
            int ii = ib + r, jj = jb + c;
            float dv = pnr[r] + tnr[c] - 2.0f * acc[r][c];
            buf[(ii + jj) * 65 + ii] = fmaxf(dv, 0.0f);
        }
    __syncthreads();

    for (int base = 0; base < 128; base += 4) {
        int tdd = base + (tid >> 6);
        int ii  = tid & 63;
        if (tdd < 127) {
            int jj = tdd - ii;
            if (jj >= 0 && jj < 64)
                g_D[DI(b, i0 + j0 + tdd, i0 + ii)] = buf[tdd * 65 + ii];
        }
    }
}

// ---------------------------------------------------------------------------
// Kernel 2: soft-DTW forward. 2 diagonals per barrier (halo X = R[d][i-1]).
// ---------------------------------------------------------------------------
__global__ __launch_bounds__(256) void fwd_kernel()
{
    __shared__ float sR[4][260];   // R[dd][k] at sR[dd&3][k+2]; [0..1] = BIG pad
    const int b = blockIdx.x;
    const int i = threadIdx.x;

    for (int q = i; q < 4 * 260; q += 256) ((float*)sR)[q] = BIGV;
    __syncthreads();

    const float* Dbase = g_D + ((size_t)b * NDIAGT + PAD) * TLEN;
    const float* Dp = Dbase + i;
    float*       Rp = g_R + ((size_t)b * NDIAGT + PAD) * TLEN + i;

    float rA[4], rB[4];   // rA[k]=D[2p], rB[k]=D[2p+1] for upcoming phase
#pragma unroll
    for (int k = 0; k < 4; k++) {
        rA[k] = Dp[(2 * k) * TLEN];
        rB[k] = Dp[(2 * k + 1) * TLEN];
    }

    auto fstep = [&](int p, int k) {
        const int d = 2 * p;
        float DY = rA[k], DZ = rB[k];
        rA[k] = Dp[(d + 8) * TLEN];
        rB[k] = Dp[(d + 9) * TLEN];
        float DXv = Dbase[(size_t)d * TLEN + (i - 1)];  // pad rows make i=0 safe

        const float* rm1 = sR[(d + 3) & 3];  // diag d-1
        const float* rm2 = sR[(d + 2) & 3];  // diag d-2

        // X = R[d][i-1] (halo)
        bool vX = (i >= 1) && (i <= d + 1) && (d - i < 255);
        float x = softmin3(rm2[i], rm1[i], rm1[i + 1]) + DXv;
        if (d == 0) x = DXv;          // cell (0,0) when vX (i==1)
        if (!vX) x = BIGV;

        // Y = R[d][i]
        bool vY = (i <= d) && (d - i < 256);
        float z1y = rm1[i + 1];
        float y = softmin3(rm2[i + 1], z1y, rm1[i + 2]) + DY;
        if (d == 0 && i == 0) y = DY;
        if (!vY) y = BIGV;

        // Z = R[d+1][i]  (needs R[d-1][i-1]=z1y, X, Y)
        bool vZ = (i <= d + 1) && (d - i < 255);
        float z = softmin3(z1y, x, y) + DZ;
        if (!vZ) z = BIGV;

        Rp[(size_t)d * TLEN]       = y;
        Rp[(size_t)(d + 1) * TLEN] = z;
        sR[d & 3][i + 2]       = y;
        sR[(d + 1) & 3][i + 2] = z;
        __syncthreads();
    };

#pragma unroll 1
    for (int g = 0; g < 63; g++) {
#pragma unroll
        for (int k = 0; k < 4; k++) fstep(g * 4 + k, k);
    }
    fstep(252, 0); fstep(253, 1); fstep(254, 2);

    // Epilogue: diag 510.
    {
        const int d = 510;
        float DY = rA[3];
        const float* rm1 = sR[(d + 3) & 3];
        const float* rm2 = sR[(d + 2) & 3];
        float y = softmin3(rm2[i + 1], rm1[i + 1], rm1[i + 2]) + DY;
        if (i < 255) y = BIGV;
        Rp[(size_t)d * TLEN] = y;
        if (i == 255) g_shape[b] = y;   // R[255,255]
    }
}

// ---------------------------------------------------------------------------
// Kernel 3: soft-DTW gradient, reverse. 2 diagonals per barrier
// (halo X = E[d][i+1]).  Q = (R - D) * KE2.
// ---------------------------------------------------------------------------
__global__ __launch_bounds__(256) void bwd_kernel()
{
    __shared__ float sE[4][260];   // position k at [k]; [256..259] = 0 pad
    __shared__ float sQ[4][260];
    __shared__ float red[16];

    const int b = blockIdx.x;
    const int i = threadIdx.x;

    for (int q = i; q < 4 * 260; q += 256) {
        ((float*)sE)[q] = 0.0f;
        ((float*)sQ)[q] = 0.0f;
    }
    __syncthreads();

    const float* Rbase = g_R + ((size_t)b * NDIAGT + PAD) * TLEN;
    const float* Dbase = g_D + ((size_t)b * NDIAGT + PAD) * TLEN;
    const float* Rp = Rbase + i;
    const float* Dp = Dbase + i;

    float rR0[4], rD0[4], rR1[4], rD1[4];
#pragma unroll
    for (int k = 0; k < 4; k++) {
        rR0[k] = Rp[(size_t)(510 - 2 * k) * TLEN];
        rD0[k] = Dp[(size_t)(510 - 2 * k) * TLEN];
        rR1[k] = Rp[(size_t)(509 - 2 * k) * TLEN];
        rD1[k] = Dp[(size_t)(509 - 2 * k) * TLEN];
    }

    float accS = 0.0f, accW = 0.0f;

    auto bstep = [&](int p, int k) {
        const int d = 510 - 2 * p;
        float R0 = rR0[k], D0 = rD0[k], R1 = rR1[k], D1 = rD1[k];
        rR0[k] = Rp[(size_t)(d - 8) * TLEN];
        rD0[k] = Dp[(size_t)(d - 8) * TLEN];
        rR1[k] = Rp[(size_t)(d - 9) * TLEN];
        rD1[k] = Dp[(size_t)(d - 9) * TLEN];
        float Rx = Rbase[(size_t)d * TLEN + (i + 1)];   // in-bounds via pad rows
        float Dx = Dbase[(size_t)d * TLEN + (i + 1)];

        const int j = d - i;
        const float* eN1 = sE[(d + 1) & 3]; const float* qN1 = sQ[(d + 1) & 3];
        const float* eN2 = sE[(d + 2) & 3]; const float* qN2 = sQ[(d + 2) & 3];

        // Y = E[d][i]
        bool vY = (i <= d) && (j < 256);
        float Y = 0.0f;
        if (vY) {
            float tY = R0 * KE2;
            float e = 0.0f;
            if (i < 255) e = fmaf(eN1[i + 1], ex2f_(qN1[i + 1] - tY), e);
            if (j < 255) e = fmaf(eN1[i],     ex2f_(qN1[i]     - tY), e);
            if (i < 255 && j < 255)
                         e = fmaf(eN2[i + 1], ex2f_(qN2[i + 1] - tY), e);
            Y = e;
        }
        if (d == 510) Y = (i == 255) ? 1.0f : 0.0f;

        // X = E[d][i+1] (halo)
        bool vX = (i < 255) && (i + 1 <= d) && (d - i - 1 < 256);
        float X = 0.0f;
        if (vX) {
            float tX = Rx * KE2;
            float e = 0.0f;
            if (i + 1 < 255) e = fmaf(eN1[i + 2], ex2f_(qN1[i + 2] - tX), e);
            if (j - 1 < 255) e = fmaf(eN1[i + 1], ex2f_(qN1[i + 1] - tX), e);
            if (i + 1 < 255 && j - 1 < 255)
                             e = fmaf(eN2[i + 2], ex2f_(qN2[i + 2] - tX), e);
            X = e;
        }
        if (d == 510) X = (i + 1 == 255) ? 1.0f : 0.0f;

        // Z = E[d-1][i]
        float QY = (R0 - D0) * KE2;
        float QX = (Rx - Dx) * KE2;
        bool vZ = (i <= d - 1) && (d - 1 - i < 256);
        float Z = 0.0f;
        if (vZ) {
            float tZ = R1 * KE2;
            float e = 0.0f;
            if (i < 255)         e = fmaf(X, ex2f_(QX - tZ), e);
            if (d - 1 - i < 255) e = fmaf(Y, ex2f_(QY - tZ), e);
            if (i < 255 && d - 1 - i < 255)
                                 e = fmaf(eN1[i + 1], ex2f_(qN1[i + 1] - tZ), e);
            Z = e;
        }

        if (vY) { accS += Y; float w = (float)(i - j);       accW = fmaf(Y, w * w, accW); }
        if (vZ) { accS += Z; float w = (float)(i - (j - 1)); accW = fmaf(Z, w * w, accW); }

        sE[d & 3][i] = Y;       sQ[d & 3][i] = QY;
        sE[(d - 1) & 3][i] = Z; sQ[(d - 1) & 3][i] = (R1 - D1) * KE2;
        __syncthreads();
    };

#pragma unroll 1
    for (int g = 0; g < 63; g++) {
#pragma unroll
        for (int k = 0; k < 4; k++) bstep(g * 4 + k, k);
    }
    bstep(252, 0); bstep(253, 1); bstep(254, 2);

    // Epilogue: diag 0 (cell (0,0); omega weight = 0).
    if (i == 0) {
        float tY = rR0[3] * KE2;
        float e = 0.0f;
        e = fmaf(sE[1][1], ex2f_(sQ[1][1] - tY), e);
        e = fmaf(sE[1][0], ex2f_(sQ[1][0] - tY), e);
        e = fmaf(sE[2][1], ex2f_(sQ[2][1] - tY), e);
        accS += e;
    }

    accW *= (1.0f / (255.0f * 255.0f));

#pragma unroll
    for (int off = 16; off; off >>= 1) {
        accS += __shfl_down_sync(0xFFFFFFFFu, accS, off);
        accW += __shfl_down_sync(0xFFFFFFFFu, accW, off);
    }
    const int w = i >> 5, l = i & 31;
    if (l == 0) { red[w] = accS; red[w + 8] = accW; }
    __syncthreads();
    if (i == 0) {
        float s = 0.0f, wv = 0.0f;
#pragma unroll
        for (int q = 0; q < 8; q++) { s += red[q]; wv += red[q + 8]; }
        g_den[b] = s;
        g_num[b] = wv;
    }
}

// ---------------------------------------------------------------------------
// Kernel 4: final scalar.
// ---------------------------------------------------------------------------
__global__ void final_kernel(float* __restrict__ out)
{
    __shared__ float red[4];
    const int t = threadIdx.x;   // 128 threads, one per batch

    float shape = g_shape[t] * (1.0f / 256.0f);
    float den   = g_den[t]   * (1.0f / 256.0f);
    float num   = g_num[t]   * (1.0f / 256.0f);
    float temporal = num / fmaxf(den, 1e-8f);
    float val = 0.5f * shape + 0.5f * temporal;

#pragma unroll
    for (int off = 16; off; off >>= 1)
        val += __shfl_down_sync(0xFFFFFFFFu, val, off);
    if ((t & 31) == 0) red[t >> 5] = val;
    __syncthreads();
    if (t == 0)
        out[0] = (red[0] + red[1] + red[2] + red[3]) * (1.0f / 128.0f);
}

// ---------------------------------------------------------------------------
extern "C" void kernel_launch(void* const* d_in, const int* in_sizes, int n_in,
                              void* d_out, int out_size)
{
    const float* preds   = (const float*)d_in[0];
    const float* targets = (const float*)d_in[1];

    dist_kernel<<<dim3(4, 4, BATCH), 256>>>(preds, targets);
    fwd_kernel<<<BATCH, 256>>>();
    bwd_kernel<<<BATCH, 256>>>();
    final_kernel<<<1, 128>>>((float*)d_out);
}